// round 16
// baseline (speedup 1.0000x reference)
#include <cuda_runtime.h>
#include <cuda_fp16.h>
#include <cstdint>

#define NV 50000
#define NE 400000
#define CN 12500
#define NROWS 100000
#define NROWSP 100096   /* 782 * 128 */
#define NTILES 782
#define PREB 148        /* fused pre-kernel blocks */
#define GGRID 296       /* persistent GEMM grid: 2 CTAs/SM */

// ---------------- scratch (static device memory) ----------------
__device__ int   d_barA;
__device__ int   d_degcnt[NV];
__device__ int   d_rowptr[NV + 1];
__device__ int   d_cursor[NV];
__device__ float d_deginv[NV];
__device__ int   d_blocksums[128];
__device__ int2  d_sorted[NE];                         // (end, val bits)
// fp16 feature images, row r = 2v+b
__device__ unsigned short d_h0x[(size_t)NROWSP * 64];  // x
__device__ unsigned short d_h0z[(size_t)NROWSP * 64];  // z0
__device__ unsigned short d_h1 [(size_t)NROWSP * 128]; // out0
__device__ unsigned short d_h1z[(size_t)NROWSP * 128]; // z1
// fp16 weight images, XOR-swizzled smem layout: [chunk][n][64] (rows of 8x16B chunks)
__device__ unsigned short d_Wimg0[2 * 128 * 64];
__device__ unsigned short d_Wimg1[4 * 128 * 64];

// ---------------- helpers ----------------
__device__ __forceinline__ uint32_t smem_u32(const void* p) {
    uint32_t a;
    asm("{ .reg .u64 t; cvta.to.shared.u64 t, %1; cvt.u32.u64 %0, t; }" : "=r"(a) : "l"(p));
    return a;
}
__device__ __forceinline__ void ldmat4(uint32_t* r, uint32_t addr) {
    asm volatile("ldmatrix.sync.aligned.m8n8.x4.shared.b16 {%0,%1,%2,%3}, [%4];"
                 : "=r"(r[0]), "=r"(r[1]), "=r"(r[2]), "=r"(r[3]) : "r"(addr));
}
__device__ __forceinline__ void mma_f16(float* d, const uint32_t* a, const uint32_t* b) {
    asm volatile("mma.sync.aligned.m16n8k16.row.col.f32.f16.f16.f32 "
                 "{%0,%1,%2,%3}, {%4,%5,%6,%7}, {%8,%9}, {%0,%1,%2,%3};"
                 : "+f"(d[0]), "+f"(d[1]), "+f"(d[2]), "+f"(d[3])
                 : "r"(a[0]), "r"(a[1]), "r"(a[2]), "r"(a[3]), "r"(b[0]), "r"(b[1]));
}
__device__ __forceinline__ void cpa16(uint32_t dst, const void* src) {
    asm volatile("cp.async.cg.shared.global [%0], [%1], 16;" :: "r"(dst), "l"(src) : "memory");
}
#define CPA_COMMIT() asm volatile("cp.async.commit_group;" ::: "memory")
#define CPA_WAIT1()  asm volatile("cp.async.wait_group 1;" ::: "memory")

__device__ __forceinline__ unsigned short hfb(float x) {
    return __half_as_ushort(__float2half_rn(x));
}
__device__ __forceinline__ uint32_t pkh(float a, float b) {
    return (uint32_t)hfb(a) | ((uint32_t)hfb(b) << 16);
}
__device__ __forceinline__ float2 h2f(uint32_t u) {
    __half2 h = *reinterpret_cast<const __half2*>(&u);
    return __half22float2(h);
}

// software grid barrier (all blocks co-resident by construction)
__device__ __forceinline__ void gbar(int* ctr, int target) {
    __syncthreads();
    __threadfence();
    if (threadIdx.x == 0) {
        atomicAdd(ctr, 1);
        while (atomicAdd(ctr, 0) < target) { }
    }
    __syncthreads();
    __threadfence();
}

// ---------------- k_pre: zero -> {Wimg, x-img, hist} -> scan -> fixup -> CSR fill ----------------
__global__ void __launch_bounds__(512) k_pre(const float* __restrict__ W0s, const float* __restrict__ W0n,
                                             const float* __restrict__ W1s, const float* __restrict__ W1n,
                                             const float* __restrict__ x,
                                             const int* __restrict__ Es, const int* __restrict__ Ee,
                                             const float* __restrict__ adj) {
    __shared__ int s[512];
    const int stride = PREB * 512;
    int tid = threadIdx.x;
    int gt = blockIdx.x * 512 + tid;

    // phase 0: zero counters
    for (int i = gt; i < NV; i += stride) { d_degcnt[i] = 0; d_cursor[i] = 0; }
    gbar(&d_barA, PREB);

    // phase 1: weight images + x image + degree histogram
    for (int it = gt; it < 49152; it += stride) {
        bool isL1 = it >= 16384;
        int loc = isL1 ? (it - 16384) : it;
        int c = loc >> 13;
        int rem = loc & 8191;
        int n = rem >> 6;
        int kl = rem & 63;
        int k = c * 64 + kl;
        float v;
        if (isL1) v = (k < 128) ? W1s[(size_t)k * 128 + n] : W1n[(size_t)(k - 128) * 128 + n];
        else      v = (k < 64)  ? W0s[(size_t)k * 128 + n] : W0n[(size_t)(k - 64) * 128 + n];
        unsigned short* img = isL1 ? d_Wimg1 : d_Wimg0;
        int q = kl >> 3;
        img[(size_t)(c * 128 + n) * 64 + ((q ^ (n & 7)) * 8 + (kl & 7))] = hfb(v);
    }
    for (int it = gt; it < NROWS * 8; it += stride) {
        int row = it >> 3, k8 = (it & 7) * 8;
        const float* src = x + ((size_t)(row & 1) * NV + (row >> 1)) * 64 + k8;
        float4 a = *(const float4*)src;
        float4 b = *(const float4*)(src + 4);
        *(uint4*)(d_h0x + (size_t)row * 64 + k8) =
            make_uint4(pkh(a.x, a.y), pkh(a.z, a.w), pkh(b.x, b.y), pkh(b.z, b.w));
    }
    for (int e = gt; e < NE; e += stride) atomicAdd(&d_degcnt[Es[e]], 1);
    gbar(&d_barA, 2 * PREB);

    // phase 2: per-block inclusive scan of degcnt (blocks 0..97 carry data)
    {
        int val = (gt < NV) ? d_degcnt[gt] : 0;
        s[tid] = val;
        __syncthreads();
        for (int off = 1; off < 512; off <<= 1) {
            int t = (tid >= off) ? s[tid - off] : 0;
            __syncthreads();
            s[tid] += t;
            __syncthreads();
        }
        if (gt < NV) d_rowptr[gt + 1] = s[tid];
        if (tid == 511 && blockIdx.x < 98) d_blocksums[blockIdx.x] = s[511];
    }
    gbar(&d_barA, 3 * PREB);

    // phase 3: redundant scan of 98 block sums + fixup + deginv
    {
        s[tid] = (tid < 98) ? d_blocksums[tid] : 0;
        __syncthreads();
        for (int off = 1; off < 512; off <<= 1) {
            int u = (tid >= off) ? s[tid - off] : 0;
            __syncthreads();
            s[tid] += u;
            __syncthreads();
        }
        int boff = (blockIdx.x > 0 && blockIdx.x < 98) ? s[blockIdx.x - 1] : 0;
        if (gt < NV) {
            d_rowptr[gt + 1] += boff;
            d_deginv[gt] = 1.0f / fmaxf((float)d_degcnt[gt], 1.0f);
        }
        if (gt == 0) d_rowptr[0] = 0;
    }
    gbar(&d_barA, 4 * PREB);

    // phase 4: CSR fill
    for (int e = gt; e < NE; e += stride) {
        int src = Es[e];
        int p = atomicAdd(&d_cursor[src], 1);
        d_sorted[d_rowptr[src] + p] = make_int2(Ee[e], __float_as_int(adj[e]));
    }
}

// ---------------- gather64: warp/node, fp16 reads, unroll-4, fp16 z0 write ----------------
__global__ void __launch_bounds__(256) k_gather64() {
    // reset the grid-barrier counter for the NEXT graph replay (k_pre has fully
    // completed by the time this kernel runs; nothing else touches d_barA).
    if (blockIdx.x == 0 && threadIdx.x == 0) d_barA = 0;
    int v = blockIdx.x * 8 + (threadIdx.x >> 5);
    int lane = threadIdx.x & 31;
    int b = lane >> 4, k = (lane & 15) * 4;
    int i = d_rowptr[v], end = d_rowptr[v + 1];
    float4 acc = make_float4(0.f, 0.f, 0.f, 0.f);
    for (; i + 4 <= end; i += 4) {
        int2 e0 = d_sorted[i],     e1 = d_sorted[i + 1];
        int2 e2 = d_sorted[i + 2], e3 = d_sorted[i + 3];
        uint2 q0 = *(const uint2*)(d_h0x + ((size_t)e0.x * 2 + b) * 64 + k);
        uint2 q1 = *(const uint2*)(d_h0x + ((size_t)e1.x * 2 + b) * 64 + k);
        uint2 q2 = *(const uint2*)(d_h0x + ((size_t)e2.x * 2 + b) * 64 + k);
        uint2 q3 = *(const uint2*)(d_h0x + ((size_t)e3.x * 2 + b) * 64 + k);
        float w0 = __int_as_float(e0.y), w1 = __int_as_float(e1.y);
        float w2 = __int_as_float(e2.y), w3 = __int_as_float(e3.y);
        float2 f;
        f = h2f(q0.x); acc.x = fmaf(w0, f.x, acc.x); acc.y = fmaf(w0, f.y, acc.y);
        f = h2f(q0.y); acc.z = fmaf(w0, f.x, acc.z); acc.w = fmaf(w0, f.y, acc.w);
        f = h2f(q1.x); acc.x = fmaf(w1, f.x, acc.x); acc.y = fmaf(w1, f.y, acc.y);
        f = h2f(q1.y); acc.z = fmaf(w1, f.x, acc.z); acc.w = fmaf(w1, f.y, acc.w);
        f = h2f(q2.x); acc.x = fmaf(w2, f.x, acc.x); acc.y = fmaf(w2, f.y, acc.y);
        f = h2f(q2.y); acc.z = fmaf(w2, f.x, acc.z); acc.w = fmaf(w2, f.y, acc.w);
        f = h2f(q3.x); acc.x = fmaf(w3, f.x, acc.x); acc.y = fmaf(w3, f.y, acc.y);
        f = h2f(q3.y); acc.z = fmaf(w3, f.x, acc.z); acc.w = fmaf(w3, f.y, acc.w);
    }
    for (; i < end; i++) {
        int2 e0 = d_sorted[i];
        float w0 = __int_as_float(e0.y);
        uint2 q0 = *(const uint2*)(d_h0x + ((size_t)e0.x * 2 + b) * 64 + k);
        float2 f;
        f = h2f(q0.x); acc.x = fmaf(w0, f.x, acc.x); acc.y = fmaf(w0, f.y, acc.y);
        f = h2f(q0.y); acc.z = fmaf(w0, f.x, acc.z); acc.w = fmaf(w0, f.y, acc.w);
    }
    float di = d_deginv[v];
    acc.x *= di; acc.y *= di; acc.z *= di; acc.w *= di;
    *(uint2*)(d_h0z + ((size_t)v * 2 + b) * 64 + k) = make_uint2(pkh(acc.x, acc.y), pkh(acc.z, acc.w));
}

// ---------------- gather128: warp/node, fp16 out0 reads (16B/lane), unroll-4, fp16 z1 write ----------------
__global__ void __launch_bounds__(256) k_gather128() {
    int v = blockIdx.x * 8 + (threadIdx.x >> 5);
    int lane = threadIdx.x & 31;
    int fo = lane * 8;
    int i = d_rowptr[v], end = d_rowptr[v + 1];
    float a[8];
#pragma unroll
    for (int j = 0; j < 8; j++) a[j] = 0.f;
    for (; i + 4 <= end; i += 4) {
        int2 e0 = d_sorted[i],     e1 = d_sorted[i + 1];
        int2 e2 = d_sorted[i + 2], e3 = d_sorted[i + 3];
        uint4 q0 = *(const uint4*)(d_h1 + (size_t)e0.x * 256 + fo);
        uint4 q1 = *(const uint4*)(d_h1 + (size_t)e1.x * 256 + fo);
        uint4 q2 = *(const uint4*)(d_h1 + (size_t)e2.x * 256 + fo);
        uint4 q3 = *(const uint4*)(d_h1 + (size_t)e3.x * 256 + fo);
        float w0 = __int_as_float(e0.y), w1 = __int_as_float(e1.y);
        float w2 = __int_as_float(e2.y), w3 = __int_as_float(e3.y);
        float2 f;
        f = h2f(q0.x); a[0] = fmaf(w0, f.x, a[0]); a[1] = fmaf(w0, f.y, a[1]);
        f = h2f(q0.y); a[2] = fmaf(w0, f.x, a[2]); a[3] = fmaf(w0, f.y, a[3]);
        f = h2f(q0.z); a[4] = fmaf(w0, f.x, a[4]); a[5] = fmaf(w0, f.y, a[5]);
        f = h2f(q0.w); a[6] = fmaf(w0, f.x, a[6]); a[7] = fmaf(w0, f.y, a[7]);
        f = h2f(q1.x); a[0] = fmaf(w1, f.x, a[0]); a[1] = fmaf(w1, f.y, a[1]);
        f = h2f(q1.y); a[2] = fmaf(w1, f.x, a[2]); a[3] = fmaf(w1, f.y, a[3]);
        f = h2f(q1.z); a[4] = fmaf(w1, f.x, a[4]); a[5] = fmaf(w1, f.y, a[5]);
        f = h2f(q1.w); a[6] = fmaf(w1, f.x, a[6]); a[7] = fmaf(w1, f.y, a[7]);
        f = h2f(q2.x); a[0] = fmaf(w2, f.x, a[0]); a[1] = fmaf(w2, f.y, a[1]);
        f = h2f(q2.y); a[2] = fmaf(w2, f.x, a[2]); a[3] = fmaf(w2, f.y, a[3]);
        f = h2f(q2.z); a[4] = fmaf(w2, f.x, a[4]); a[5] = fmaf(w2, f.y, a[5]);
        f = h2f(q2.w); a[6] = fmaf(w2, f.x, a[6]); a[7] = fmaf(w2, f.y, a[7]);
        f = h2f(q3.x); a[0] = fmaf(w3, f.x, a[0]); a[1] = fmaf(w3, f.y, a[1]);
        f = h2f(q3.y); a[2] = fmaf(w3, f.x, a[2]); a[3] = fmaf(w3, f.y, a[3]);
        f = h2f(q3.z); a[4] = fmaf(w3, f.x, a[4]); a[5] = fmaf(w3, f.y, a[5]);
        f = h2f(q3.w); a[6] = fmaf(w3, f.x, a[6]); a[7] = fmaf(w3, f.y, a[7]);
    }
    for (; i < end; i++) {
        int2 e0 = d_sorted[i];
        float w0 = __int_as_float(e0.y);
        uint4 q0 = *(const uint4*)(d_h1 + (size_t)e0.x * 256 + fo);
        float2 f;
        f = h2f(q0.x); a[0] = fmaf(w0, f.x, a[0]); a[1] = fmaf(w0, f.y, a[1]);
        f = h2f(q0.y); a[2] = fmaf(w0, f.x, a[2]); a[3] = fmaf(w0, f.y, a[3]);
        f = h2f(q0.z); a[4] = fmaf(w0, f.x, a[4]); a[5] = fmaf(w0, f.y, a[5]);
        f = h2f(q0.w); a[6] = fmaf(w0, f.x, a[6]); a[7] = fmaf(w0, f.y, a[7]);
    }
    float di = d_deginv[v];
#pragma unroll
    for (int j = 0; j < 8; j++) a[j] *= di;
    int rz = 2 * v + (lane >> 4);
    int f0i = (lane & 15) * 8;
    *(uint4*)(d_h1z + (size_t)rz * 128 + f0i) =
        make_uint4(pkh(a[0], a[1]), pkh(a[2], a[3]), pkh(a[4], a[5]), pkh(a[6], a[7]));
}

// ---------------- persistent tensor-core GEMM: resident B, 3-stage A ring ----------------
// L0: epilogue writes out0 fp16 image (bias + leaky).
// L1: epilogue pools directly into `out` (+=), weighted by asgnVal, via shfl reduction.
// smem: [0,1024) bias; [1024) A ring 3x16384; [50176) B resident NC x 16384.
template <int NC, bool L0F>
__global__ void __launch_bounds__(256, 2) k_gemm(const float* __restrict__ bias,
                                                 const float* __restrict__ asgnVal,
                                                 float* __restrict__ out) {
    extern __shared__ unsigned char sm[];
    const int SA = 1024;
    const int SB = 1024 + 3 * 16384;
    int tid = threadIdx.x;
    int wid = tid >> 5, lane = tid & 31;
    int wm = (wid & 3) * 32, wn = (wid >> 2) * 64;
    uint32_t smb = smem_u32(sm);
    const unsigned short* wimg = L0F ? d_Wimg0 : d_Wimg1;

    int bid = blockIdx.x;
    int nt = 0;
    for (int t = bid; t < NTILES; t += GGRID) nt++;
    const int total = nt * NC;

    auto Abase = [&](int t, int c, int rowl) -> const unsigned short* {
        size_t r = (size_t)(t * 128 + rowl);
        if (L0F) return (c == 0 ? d_h0x : d_h0z) + r * 64;
        else     return (c < 2 ? d_h1 + c * 64 : d_h1z + (c - 2) * 64) + r * 128;
    };

    int pi = 0;
    auto issueA = [&]() {
        if (pi < total) {
            int t = bid + (pi / NC) * GGRID;
            int c = pi % NC;
            int s = pi % 3;
#pragma unroll
            for (int i = 0; i < 4; i++) {
                int seg = tid + i * 256;
                int rowl = seg >> 3, q = seg & 7;
                cpa16(smb + SA + s * 16384 + rowl * 128 + ((q ^ (rowl & 7)) << 4),
                      Abase(t, c, rowl) + q * 8);
            }
            pi++;
        }
        CPA_COMMIT();
    };

    {
        const unsigned char* bsrc = (const unsigned char*)wimg;
        for (int seg = tid; seg < NC * 1024; seg += 256)
            cpa16(smb + SB + seg * 16, bsrc + seg * 16);
        CPA_COMMIT();
        if (tid < 128) ((float*)sm)[tid] = bias[tid];
    }
    issueA();
    issueA();

    int a_r = wm + (lane & 15);
    int a_k = (lane >> 4) << 3;
    int b_n = wn + (lane & 7) + ((lane >> 4) << 3);
    int b_k = ((lane >> 3) & 1) << 3;

    float acc[2][8][4];
    int ci = 0;
    for (int t = bid; t < NTILES; t += GGRID) {
#pragma unroll
        for (int m = 0; m < 2; m++)
#pragma unroll
            for (int nf = 0; nf < 8; nf++)
#pragma unroll
                for (int q = 0; q < 4; q++) acc[m][nf][q] = 0.f;

#pragma unroll
        for (int c = 0; c < NC; c++, ci++) {
            CPA_WAIT1();
            __syncthreads();
            issueA();
            uint32_t aB = smb + SA + (ci % 3) * 16384;
            uint32_t bB = smb + SB + c * 16384;
#pragma unroll
            for (int ks = 0; ks < 4; ks++) {
                int k0 = ks * 16;
                uint32_t ah[2][4];
#pragma unroll
                for (int m = 0; m < 2; m++) {
                    int row = a_r + m * 16;
                    int cc = (k0 + a_k) >> 3;
                    ldmat4(ah[m], aB + (uint32_t)(row * 128 + ((cc ^ (row & 7)) << 4)));
                }
                uint32_t bh[8][2];
#pragma unroll
                for (int g = 0; g < 4; g++) {
                    int row = b_n + g * 16;
                    int cc = (k0 + b_k) >> 3;
                    uint32_t tr[4];
                    ldmat4(tr, bB + (uint32_t)(row * 128 + ((cc ^ (row & 7)) << 4)));
                    bh[2 * g][0] = tr[0]; bh[2 * g][1] = tr[1];
                    bh[2 * g + 1][0] = tr[2]; bh[2 * g + 1][1] = tr[3];
                }
#pragma unroll
                for (int m = 0; m < 2; m++)
#pragma unroll
                    for (int nf = 0; nf < 8; nf++) mma_f16(acc[m][nf], ah[m], bh[nf]);
            }
        }

        const float* sbias = (const float*)sm;
#pragma unroll
        for (int m = 0; m < 2; m++) {
            int base = t * 128 + wm + m * 16;
            int ro = lane >> 2;
            int r0 = base + ro;
            if (L0F) {
#pragma unroll
                for (int nf = 0; nf < 8; nf++) {
                    int col = wn + nf * 8 + (lane & 3) * 2;
                    float bx = sbias[col], by = sbias[col + 1];
                    float o0 = acc[m][nf][0] + bx, o1 = acc[m][nf][1] + by;
                    float o2 = acc[m][nf][2] + bx, o3 = acc[m][nf][3] + by;
                    o0 = (o0 >= 0.f) ? o0 : 0.2f * o0;
                    o1 = (o1 >= 0.f) ? o1 : 0.2f * o1;
                    o2 = (o2 >= 0.f) ? o2 : 0.2f * o2;
                    o3 = (o3 >= 0.f) ? o3 : 0.2f * o3;
                    if (r0 < NROWS)
                        *(uint32_t*)(d_h1 + (size_t)r0 * 128 + col) = pkh(o0, o1);
                    if (r0 + 8 < NROWS)
                        *(uint32_t*)(d_h1 + (size_t)(r0 + 8) * 128 + col) = pkh(o2, o3);
                }
            } else {
                // pooled epilogue: weight each row by its assignment value, reduce
                // across the 4 lanes holding rows of the same (coarse, batch) class.
                int v0 = r0 >> 1;              // fine node of row r0
                int v1 = (r0 + 8) >> 1;        // fine node of row r0+8
                float w0 = (v0 < NV) ? asgnVal[v0] : 0.f;
                float w1 = (v1 < NV) ? asgnVal[v1] : 0.f;
                int c0 = base >> 3;            // coarse for rows base..base+7
                int c1 = c0 + 1;               // coarse for rows base+8..base+15
                int b = ro & 1;
#pragma unroll
                for (int nf = 0; nf < 8; nf++) {
                    int col = wn + nf * 8 + (lane & 3) * 2;
                    float bx = sbias[col], by = sbias[col + 1];
                    float s00 = w0 * (acc[m][nf][0] + bx);
                    float s01 = w0 * (acc[m][nf][1] + by);
                    float s10 = w1 * (acc[m][nf][2] + bx);
                    float s11 = w1 * (acc[m][nf][3] + by);
                    s00 += __shfl_xor_sync(0xFFFFFFFFu, s00, 8);
                    s01 += __shfl_xor_sync(0xFFFFFFFFu, s01, 8);
                    s10 += __shfl_xor_sync(0xFFFFFFFFu, s10, 8);
                    s11 += __shfl_xor_sync(0xFFFFFFFFu, s11, 8);
                    s00 += __shfl_xor_sync(0xFFFFFFFFu, s00, 16);
                    s01 += __shfl_xor_sync(0xFFFFFFFFu, s01, 16);
                    s10 += __shfl_xor_sync(0xFFFFFFFFu, s10, 16);
                    s11 += __shfl_xor_sync(0xFFFFFFFFu, s11, 16);
                    if (ro < 2) {
                        if (c0 < CN) {
                            float* p = out + ((size_t)b * CN + c0) * 128 + col;
                            p[0] += s00; p[1] += s01;
                        }
                        if (c1 < CN) {
                            float* p = out + ((size_t)b * CN + c1) * 128 + col;
                            p[0] += s10; p[1] += s11;
                        }
                    }
                }
            }
        }
    }
}

// ---------------- k_finalres: out = pool(x) @ W_res + sw * b_res  (runs BEFORE gemm1) ----------------
__global__ void __launch_bounds__(256) k_finalres(const float* __restrict__ x,
                                                  const int* __restrict__ asgnIdx,
                                                  const float* __restrict__ asgnVal,
                                                  const float* __restrict__ Wres,
                                                  const float* __restrict__ bres,
                                                  float* __restrict__ out) {
    __shared__ float xps[4][64];
    int sub = threadIdx.x >> 6;
    int p = threadIdx.x & 63;
    int r = blockIdx.x * 4 + sub;
    bool ok = r < 2 * CN;
    int c = r >> 1, b = r & 1;
    const int* fine = asgnIdx + NV;
    float sw = 0.f;
    if (ok) {
        int i0 = 4 * c;
        float a = 0.f;
#pragma unroll
        for (int j = 0; j < 4; j++) {
            int f = fine[i0 + j];
            float w = asgnVal[i0 + j];
            a = fmaf(w, x[((size_t)b * NV + f) * 64 + p], a);
            sw += w;
        }
        xps[sub][p] = a;
    }
    __syncthreads();
    if (ok) {
        float2 br = *(const float2*)(bres + 2 * p);
        float accx = sw * br.x;
        float accy = sw * br.y;
#pragma unroll 8
        for (int k = 0; k < 64; k++) {
            float xk = xps[sub][k];
            float2 w2 = *(const float2*)(Wres + k * 128 + 2 * p);
            accx = fmaf(xk, w2.x, accx);
            accy = fmaf(xk, w2.y, accy);
        }
        *(float2*)(out + ((size_t)b * CN + c) * 128 + 2 * p) = make_float2(accx, accy);
    }
}

// ---------------- launch ----------------
extern "C" void kernel_launch(void* const* d_in, const int* in_sizes, int n_in,
                              void* d_out, int out_size) {
    const float* x       = (const float*)d_in[0];
    const float* adjVal  = (const float*)d_in[1];
    const int*   E_start = (const int*)d_in[3];
    const int*   E_end   = (const int*)d_in[4];
    const int*   asgnIdx = (const int*)d_in[5];
    const float* asgnVal = (const float*)d_in[6];
    const float* W_res   = (const float*)d_in[7];
    const float* b_res   = (const float*)d_in[8];
    const float* W0s     = (const float*)d_in[9];
    const float* W0n     = (const float*)d_in[10];
    const float* b0      = (const float*)d_in[11];
    const float* W1s     = (const float*)d_in[12];
    const float* W1n     = (const float*)d_in[13];
    const float* b1      = (const float*)d_in[14];
    float* out = (float*)d_out;

    const int smG0 = 1024 + 3 * 16384 + 2 * 16384;   // 82944
    const int smG1 = 1024 + 3 * 16384 + 4 * 16384;   // 115712 (2 CTAs/SM)
    cudaFuncSetAttribute(k_gemm<2, true>,  cudaFuncAttributeMaxDynamicSharedMemorySize, smG0);
    cudaFuncSetAttribute(k_gemm<4, false>, cudaFuncAttributeMaxDynamicSharedMemorySize, smG1);

    k_pre<<<PREB, 512>>>(W0s, W0n, W1s, W1n, x, E_start, E_end, adjVal);        // 0
    k_gather64<<<NV / 8, 256>>>();                                              // 1 (also resets d_barA)
    k_gemm<2, true><<<GGRID, 256, smG0>>>(b0, nullptr, nullptr);                // 2
    k_gather128<<<NV / 8, 256>>>();                                             // 3 <- ncu capture slot
    k_finalres<<<(2 * CN + 3) / 4, 256>>>(x, asgnIdx, asgnVal, W_res, b_res, out); // 4
    k_gemm<4, false><<<GGRID, 256, smG1>>>(b1, asgnVal, out);                   // 5
}

// round 17
// speedup vs baseline: 1.1368x; 1.1368x over previous
#include <cuda_runtime.h>
#include <cuda_fp16.h>
#include <cstdint>

#define NV 50000
#define NE 400000
#define CN 12500
#define NROWS 100000
#define NROWSP 100096   /* 782 * 128 */
#define NTILES 782
#define PREB 148        /* fused pre-kernel blocks */
#define GGRID 296       /* persistent GEMM grid: 2 CTAs/SM */

// ---------------- scratch (static device memory; .bss => zero on module load) ----------------
__device__ int   d_barA;
__device__ int   d_degcnt[NV];
__device__ int   d_rowptr[NV + 1];
__device__ int   d_cursor[NV];
__device__ float d_deginv[NV];
__device__ int   d_blocksums[128];
__device__ int2  d_sorted[NE];                         // (end, val bits)
// fp16 feature images, row r = 2v+b
__device__ unsigned short d_h0x[(size_t)NROWSP * 64];  // x
__device__ unsigned short d_h0z[(size_t)NROWSP * 64];  // z0
__device__ unsigned short d_h1 [(size_t)NROWSP * 128]; // out0, then out1 (in-place)
__device__ unsigned short d_h1z[(size_t)NROWSP * 128]; // z1
// fp16 weight images, XOR-swizzled smem layout: [chunk][n][64] (rows of 8x16B chunks)
__device__ unsigned short d_Wimg0[2 * 128 * 64];
__device__ unsigned short d_Wimg1[4 * 128 * 64];

// ---------------- helpers ----------------
__device__ __forceinline__ uint32_t smem_u32(const void* p) {
    uint32_t a;
    asm("{ .reg .u64 t; cvta.to.shared.u64 t, %1; cvt.u32.u64 %0, t; }" : "=r"(a) : "l"(p));
    return a;
}
__device__ __forceinline__ void ldmat4(uint32_t* r, uint32_t addr) {
    asm volatile("ldmatrix.sync.aligned.m8n8.x4.shared.b16 {%0,%1,%2,%3}, [%4];"
                 : "=r"(r[0]), "=r"(r[1]), "=r"(r[2]), "=r"(r[3]) : "r"(addr));
}
__device__ __forceinline__ void mma_f16(float* d, const uint32_t* a, const uint32_t* b) {
    asm volatile("mma.sync.aligned.m16n8k16.row.col.f32.f16.f16.f32 "
                 "{%0,%1,%2,%3}, {%4,%5,%6,%7}, {%8,%9}, {%0,%1,%2,%3};"
                 : "+f"(d[0]), "+f"(d[1]), "+f"(d[2]), "+f"(d[3])
                 : "r"(a[0]), "r"(a[1]), "r"(a[2]), "r"(a[3]), "r"(b[0]), "r"(b[1]));
}
__device__ __forceinline__ void cpa16(uint32_t dst, const void* src) {
    asm volatile("cp.async.cg.shared.global [%0], [%1], 16;" :: "r"(dst), "l"(src) : "memory");
}
#define CPA_COMMIT() asm volatile("cp.async.commit_group;" ::: "memory")
#define CPA_WAIT1()  asm volatile("cp.async.wait_group 1;" ::: "memory")

__device__ __forceinline__ unsigned short hfb(float x) {
    return __half_as_ushort(__float2half_rn(x));
}
__device__ __forceinline__ uint32_t pkh(float a, float b) {
    return (uint32_t)hfb(a) | ((uint32_t)hfb(b) << 16);
}
__device__ __forceinline__ float2 h2f(uint32_t u) {
    __half2 h = *reinterpret_cast<const __half2*>(&u);
    return __half22float2(h);
}

// software grid barrier (all blocks co-resident by construction)
__device__ __forceinline__ void gbar(int* ctr, int target) {
    __syncthreads();
    __threadfence();
    if (threadIdx.x == 0) {
        atomicAdd(ctr, 1);
        while (atomicAdd(ctr, 0) < target) { }
    }
    __syncthreads();
    __threadfence();
}

// ---------------- k_pre: {Wimg, x-img, hist} -> scan -> fixup -> CSR fill ----------------
// d_degcnt/d_cursor/d_barA are pre-zeroed: first call by .bss init, replays by k_final/k_gather64.
__global__ void __launch_bounds__(512) k_pre(const float* __restrict__ W0s, const float* __restrict__ W0n,
                                             const float* __restrict__ W1s, const float* __restrict__ W1n,
                                             const float* __restrict__ x,
                                             const int* __restrict__ Es, const int* __restrict__ Ee,
                                             const float* __restrict__ adj) {
    __shared__ int s[512];
    const int stride = PREB * 512;
    int tid = threadIdx.x;
    int gt = blockIdx.x * 512 + tid;

    // phase 0: weight images + x image + degree histogram
    for (int it = gt; it < 49152; it += stride) {
        bool isL1 = it >= 16384;
        int loc = isL1 ? (it - 16384) : it;
        int c = loc >> 13;
        int rem = loc & 8191;
        int n = rem >> 6;
        int kl = rem & 63;
        int k = c * 64 + kl;
        float v;
        if (isL1) v = (k < 128) ? W1s[(size_t)k * 128 + n] : W1n[(size_t)(k - 128) * 128 + n];
        else      v = (k < 64)  ? W0s[(size_t)k * 128 + n] : W0n[(size_t)(k - 64) * 128 + n];
        unsigned short* img = isL1 ? d_Wimg1 : d_Wimg0;
        int q = kl >> 3;
        img[(size_t)(c * 128 + n) * 64 + ((q ^ (n & 7)) * 8 + (kl & 7))] = hfb(v);
    }
    for (int it = gt; it < NROWS * 8; it += stride) {
        int row = it >> 3, k8 = (it & 7) * 8;
        const float* src = x + ((size_t)(row & 1) * NV + (row >> 1)) * 64 + k8;
        float4 a = *(const float4*)src;
        float4 b = *(const float4*)(src + 4);
        *(uint4*)(d_h0x + (size_t)row * 64 + k8) =
            make_uint4(pkh(a.x, a.y), pkh(a.z, a.w), pkh(b.x, b.y), pkh(b.z, b.w));
    }
    for (int e = gt; e < NE; e += stride) atomicAdd(&d_degcnt[Es[e]], 1);
    gbar(&d_barA, PREB);

    // phase 1: per-block inclusive scan of degcnt (blocks 0..97 carry data)
    {
        int val = (gt < NV) ? d_degcnt[gt] : 0;
        s[tid] = val;
        __syncthreads();
        for (int off = 1; off < 512; off <<= 1) {
            int t = (tid >= off) ? s[tid - off] : 0;
            __syncthreads();
            s[tid] += t;
            __syncthreads();
        }
        if (gt < NV) d_rowptr[gt + 1] = s[tid];
        if (tid == 511 && blockIdx.x < 98) d_blocksums[blockIdx.x] = s[511];
    }
    gbar(&d_barA, 2 * PREB);

    // phase 2: redundant scan of 98 block sums + fixup + deginv
    {
        s[tid] = (tid < 98) ? d_blocksums[tid] : 0;
        __syncthreads();
        for (int off = 1; off < 512; off <<= 1) {
            int u = (tid >= off) ? s[tid - off] : 0;
            __syncthreads();
            s[tid] += u;
            __syncthreads();
        }
        int boff = (blockIdx.x > 0 && blockIdx.x < 98) ? s[blockIdx.x - 1] : 0;
        if (gt < NV) {
            d_rowptr[gt + 1] += boff;
            d_deginv[gt] = 1.0f / fmaxf((float)d_degcnt[gt], 1.0f);
        }
        if (gt == 0) d_rowptr[0] = 0;
    }
    gbar(&d_barA, 3 * PREB);

    // phase 3: CSR fill
    for (int e = gt; e < NE; e += stride) {
        int src = Es[e];
        int p = atomicAdd(&d_cursor[src], 1);
        d_sorted[d_rowptr[src] + p] = make_int2(Ee[e], __float_as_int(adj[e]));
    }
}

// ---------------- gather64: warp/node, fp16 reads, unroll-4, fp16 z0 write ----------------
__global__ void __launch_bounds__(256) k_gather64() {
    // reset the grid-barrier counter for the NEXT replay (k_pre is fully done here)
    if (blockIdx.x == 0 && threadIdx.x == 0) d_barA = 0;
    int v = blockIdx.x * 8 + (threadIdx.x >> 5);
    int lane = threadIdx.x & 31;
    int b = lane >> 4, k = (lane & 15) * 4;
    int i = d_rowptr[v], end = d_rowptr[v + 1];
    float4 acc = make_float4(0.f, 0.f, 0.f, 0.f);
    for (; i + 4 <= end; i += 4) {
        int2 e0 = d_sorted[i],     e1 = d_sorted[i + 1];
        int2 e2 = d_sorted[i + 2], e3 = d_sorted[i + 3];
        uint2 q0 = *(const uint2*)(d_h0x + ((size_t)e0.x * 2 + b) * 64 + k);
        uint2 q1 = *(const uint2*)(d_h0x + ((size_t)e1.x * 2 + b) * 64 + k);
        uint2 q2 = *(const uint2*)(d_h0x + ((size_t)e2.x * 2 + b) * 64 + k);
        uint2 q3 = *(const uint2*)(d_h0x + ((size_t)e3.x * 2 + b) * 64 + k);
        float w0 = __int_as_float(e0.y), w1 = __int_as_float(e1.y);
        float w2 = __int_as_float(e2.y), w3 = __int_as_float(e3.y);
        float2 f;
        f = h2f(q0.x); acc.x = fmaf(w0, f.x, acc.x); acc.y = fmaf(w0, f.y, acc.y);
        f = h2f(q0.y); acc.z = fmaf(w0, f.x, acc.z); acc.w = fmaf(w0, f.y, acc.w);
        f = h2f(q1.x); acc.x = fmaf(w1, f.x, acc.x); acc.y = fmaf(w1, f.y, acc.y);
        f = h2f(q1.y); acc.z = fmaf(w1, f.x, acc.z); acc.w = fmaf(w1, f.y, acc.w);
        f = h2f(q2.x); acc.x = fmaf(w2, f.x, acc.x); acc.y = fmaf(w2, f.y, acc.y);
        f = h2f(q2.y); acc.z = fmaf(w2, f.x, acc.z); acc.w = fmaf(w2, f.y, acc.w);
        f = h2f(q3.x); acc.x = fmaf(w3, f.x, acc.x); acc.y = fmaf(w3, f.y, acc.y);
        f = h2f(q3.y); acc.z = fmaf(w3, f.x, acc.z); acc.w = fmaf(w3, f.y, acc.w);
    }
    for (; i < end; i++) {
        int2 e0 = d_sorted[i];
        float w0 = __int_as_float(e0.y);
        uint2 q0 = *(const uint2*)(d_h0x + ((size_t)e0.x * 2 + b) * 64 + k);
        float2 f;
        f = h2f(q0.x); acc.x = fmaf(w0, f.x, acc.x); acc.y = fmaf(w0, f.y, acc.y);
        f = h2f(q0.y); acc.z = fmaf(w0, f.x, acc.z); acc.w = fmaf(w0, f.y, acc.w);
    }
    float di = d_deginv[v];
    acc.x *= di; acc.y *= di; acc.z *= di; acc.w *= di;
    *(uint2*)(d_h0z + ((size_t)v * 2 + b) * 64 + k) = make_uint2(pkh(acc.x, acc.y), pkh(acc.z, acc.w));
}

// ---------------- gather128: warp/node, fp16 out0 reads (16B/lane), unroll-4, fp16 z1 write ----------------
__global__ void __launch_bounds__(256) k_gather128() {
    int v = blockIdx.x * 8 + (threadIdx.x >> 5);
    int lane = threadIdx.x & 31;
    int fo = lane * 8;
    int i = d_rowptr[v], end = d_rowptr[v + 1];
    float a[8];
#pragma unroll
    for (int j = 0; j < 8; j++) a[j] = 0.f;
    for (; i + 4 <= end; i += 4) {
        int2 e0 = d_sorted[i],     e1 = d_sorted[i + 1];
        int2 e2 = d_sorted[i + 2], e3 = d_sorted[i + 3];
        uint4 q0 = *(const uint4*)(d_h1 + (size_t)e0.x * 256 + fo);
        uint4 q1 = *(const uint4*)(d_h1 + (size_t)e1.x * 256 + fo);
        uint4 q2 = *(const uint4*)(d_h1 + (size_t)e2.x * 256 + fo);
        uint4 q3 = *(const uint4*)(d_h1 + (size_t)e3.x * 256 + fo);
        float w0 = __int_as_float(e0.y), w1 = __int_as_float(e1.y);
        float w2 = __int_as_float(e2.y), w3 = __int_as_float(e3.y);
        float2 f;
        f = h2f(q0.x); a[0] = fmaf(w0, f.x, a[0]); a[1] = fmaf(w0, f.y, a[1]);
        f = h2f(q0.y); a[2] = fmaf(w0, f.x, a[2]); a[3] = fmaf(w0, f.y, a[3]);
        f = h2f(q0.z); a[4] = fmaf(w0, f.x, a[4]); a[5] = fmaf(w0, f.y, a[5]);
        f = h2f(q0.w); a[6] = fmaf(w0, f.x, a[6]); a[7] = fmaf(w0, f.y, a[7]);
        f = h2f(q1.x); a[0] = fmaf(w1, f.x, a[0]); a[1] = fmaf(w1, f.y, a[1]);
        f = h2f(q1.y); a[2] = fmaf(w1, f.x, a[2]); a[3] = fmaf(w1, f.y, a[3]);
        f = h2f(q1.z); a[4] = fmaf(w1, f.x, a[4]); a[5] = fmaf(w1, f.y, a[5]);
        f = h2f(q1.w); a[6] = fmaf(w1, f.x, a[6]); a[7] = fmaf(w1, f.y, a[7]);
        f = h2f(q2.x); a[0] = fmaf(w2, f.x, a[0]); a[1] = fmaf(w2, f.y, a[1]);
        f = h2f(q2.y); a[2] = fmaf(w2, f.x, a[2]); a[3] = fmaf(w2, f.y, a[3]);
        f = h2f(q2.z); a[4] = fmaf(w2, f.x, a[4]); a[5] = fmaf(w2, f.y, a[5]);
        f = h2f(q2.w); a[6] = fmaf(w2, f.x, a[6]); a[7] = fmaf(w2, f.y, a[7]);
        f = h2f(q3.x); a[0] = fmaf(w3, f.x, a[0]); a[1] = fmaf(w3, f.y, a[1]);
        f = h2f(q3.y); a[2] = fmaf(w3, f.x, a[2]); a[3] = fmaf(w3, f.y, a[3]);
        f = h2f(q3.z); a[4] = fmaf(w3, f.x, a[4]); a[5] = fmaf(w3, f.y, a[5]);
        f = h2f(q3.w); a[6] = fmaf(w3, f.x, a[6]); a[7] = fmaf(w3, f.y, a[7]);
    }
    for (; i < end; i++) {
        int2 e0 = d_sorted[i];
        float w0 = __int_as_float(e0.y);
        uint4 q0 = *(const uint4*)(d_h1 + (size_t)e0.x * 256 + fo);
        float2 f;
        f = h2f(q0.x); a[0] = fmaf(w0, f.x, a[0]); a[1] = fmaf(w0, f.y, a[1]);
        f = h2f(q0.y); a[2] = fmaf(w0, f.x, a[2]); a[3] = fmaf(w0, f.y, a[3]);
        f = h2f(q0.z); a[4] = fmaf(w0, f.x, a[4]); a[5] = fmaf(w0, f.y, a[5]);
        f = h2f(q0.w); a[6] = fmaf(w0, f.x, a[6]); a[7] = fmaf(w0, f.y, a[7]);
    }
    float di = d_deginv[v];
#pragma unroll
    for (int j = 0; j < 8; j++) a[j] *= di;
    int rz = 2 * v + (lane >> 4);
    int f0i = (lane & 15) * 8;
    *(uint4*)(d_h1z + (size_t)rz * 128 + f0i) =
        make_uint4(pkh(a[0], a[1]), pkh(a[2], a[3]), pkh(a[4], a[5]), pkh(a[6], a[7]));
}

// ---------------- persistent tensor-core GEMM (proven config): resident B, 3-stage A ring ----------------
// smem: [0,1024) bias; [1024) A ring 3x16384; [50176) B resident NC x 16384.
template <int NC, bool L0F>
__global__ void __launch_bounds__(256, 2) k_gemm(const float* __restrict__ bias) {
    extern __shared__ unsigned char sm[];
    const int SA = 1024;
    const int SB = 1024 + 3 * 16384;
    int tid = threadIdx.x;
    int wid = tid >> 5, lane = tid & 31;
    int wm = (wid & 3) * 32, wn = (wid >> 2) * 64;
    uint32_t smb = smem_u32(sm);
    const unsigned short* wimg = L0F ? d_Wimg0 : d_Wimg1;

    int bid = blockIdx.x;
    int nt = 0;
    for (int t = bid; t < NTILES; t += GGRID) nt++;
    const int total = nt * NC;

    auto Abase = [&](int t, int c, int rowl) -> const unsigned short* {
        size_t r = (size_t)(t * 128 + rowl);
        if (L0F) return (c == 0 ? d_h0x : d_h0z) + r * 64;
        else     return (c < 2 ? d_h1 + c * 64 : d_h1z + (c - 2) * 64) + r * 128;
    };

    int pi = 0;
    auto issueA = [&]() {
        if (pi < total) {
            int t = bid + (pi / NC) * GGRID;
            int c = pi % NC;
            int s = pi % 3;
#pragma unroll
            for (int i = 0; i < 4; i++) {
                int seg = tid + i * 256;
                int rowl = seg >> 3, q = seg & 7;
                cpa16(smb + SA + s * 16384 + rowl * 128 + ((q ^ (rowl & 7)) << 4),
                      Abase(t, c, rowl) + q * 8);
            }
            pi++;
        }
        CPA_COMMIT();
    };

    {
        const unsigned char* bsrc = (const unsigned char*)wimg;
        for (int seg = tid; seg < NC * 1024; seg += 256)
            cpa16(smb + SB + seg * 16, bsrc + seg * 16);
        CPA_COMMIT();
        if (tid < 128) ((float*)sm)[tid] = bias[tid];
    }
    issueA();
    issueA();

    int a_r = wm + (lane & 15);
    int a_k = (lane >> 4) << 3;
    int b_n = wn + (lane & 7) + ((lane >> 4) << 3);
    int b_k = ((lane >> 3) & 1) << 3;

    float acc[2][8][4];
    int ci = 0;
    for (int t = bid; t < NTILES; t += GGRID) {
#pragma unroll
        for (int m = 0; m < 2; m++)
#pragma unroll
            for (int nf = 0; nf < 8; nf++)
#pragma unroll
                for (int q = 0; q < 4; q++) acc[m][nf][q] = 0.f;

#pragma unroll
        for (int c = 0; c < NC; c++, ci++) {
            CPA_WAIT1();
            __syncthreads();
            issueA();
            uint32_t aB = smb + SA + (ci % 3) * 16384;
            uint32_t bB = smb + SB + c * 16384;
#pragma unroll
            for (int ks = 0; ks < 4; ks++) {
                int k0 = ks * 16;
                uint32_t ah[2][4];
#pragma unroll
                for (int m = 0; m < 2; m++) {
                    int row = a_r + m * 16;
                    int cc = (k0 + a_k) >> 3;
                    ldmat4(ah[m], aB + (uint32_t)(row * 128 + ((cc ^ (row & 7)) << 4)));
                }
                uint32_t bh[8][2];
#pragma unroll
                for (int g = 0; g < 4; g++) {
                    int row = b_n + g * 16;
                    int cc = (k0 + b_k) >> 3;
                    uint32_t tr[4];
                    ldmat4(tr, bB + (uint32_t)(row * 128 + ((cc ^ (row & 7)) << 4)));
                    bh[2 * g][0] = tr[0]; bh[2 * g][1] = tr[1];
                    bh[2 * g + 1][0] = tr[2]; bh[2 * g + 1][1] = tr[3];
                }
#pragma unroll
                for (int m = 0; m < 2; m++)
#pragma unroll
                    for (int nf = 0; nf < 8; nf++) mma_f16(acc[m][nf], ah[m], bh[nf]);
            }
        }

        const float* sbias = (const float*)sm;
#pragma unroll
        for (int m = 0; m < 2; m++) {
            int r0 = t * 128 + wm + m * 16 + (lane >> 2);
#pragma unroll
            for (int nf = 0; nf < 8; nf++) {
                int col = wn + nf * 8 + (lane & 3) * 2;
                float bx = sbias[col], by = sbias[col + 1];
                float o0 = acc[m][nf][0] + bx, o1 = acc[m][nf][1] + by;
                float o2 = acc[m][nf][2] + bx, o3 = acc[m][nf][3] + by;
                if (L0F) {
                    o0 = (o0 >= 0.f) ? o0 : 0.2f * o0;
                    o1 = (o1 >= 0.f) ? o1 : 0.2f * o1;
                    o2 = (o2 >= 0.f) ? o2 : 0.2f * o2;
                    o3 = (o3 >= 0.f) ? o3 : 0.2f * o3;
                }
                if (r0 < NROWS)
                    *(uint32_t*)(d_h1 + (size_t)r0 * 128 + col) = pkh(o0, o1);
                if (r0 + 8 < NROWS)
                    *(uint32_t*)(d_h1 + (size_t)(r0 + 8) * 128 + col) = pkh(o2, o3);
            }
        }
    }
}

// ---------------- final: pool(out1 fp16) + (pool(x) @ W_res + sw * b_res); zero counters for replay ----------------
__global__ void __launch_bounds__(256) k_final(const float* __restrict__ x,
                                               const int* __restrict__ asgnIdx,
                                               const float* __restrict__ asgnVal,
                                               const float* __restrict__ Wres,
                                               const float* __restrict__ bres,
                                               float* __restrict__ out) {
    __shared__ float xps[4][64];
    // zero histogram/cursor for the NEXT graph replay (k_pre is long done; nothing
    // else reads these after phase computations). 6250 blocks x 256 covers 2*NV ints.
    {
        int z = blockIdx.x * 256 + threadIdx.x;
        if (z < NV) { d_degcnt[z] = 0; d_cursor[z] = 0; }
        else if (z < 2 * NV) { int z2 = z - NV; d_degcnt[z2 + 0] = d_degcnt[z2 + 0]; } // no-op filler
    }
    int sub = threadIdx.x >> 6;
    int p = threadIdx.x & 63;
    int r = blockIdx.x * 4 + sub;
    bool ok = r < 2 * CN;
    int c = r >> 1, b = r & 1;
    const int* fine = asgnIdx + NV;
    float sw = 0.f;
    float2 p1 = make_float2(0.f, 0.f);
    if (ok) {
        int i0 = 4 * c;
        float a = 0.f;
#pragma unroll
        for (int j = 0; j < 4; j++) {
            int f = fine[i0 + j];
            float w = asgnVal[i0 + j];
            a = fmaf(w, x[((size_t)b * NV + f) * 64 + p], a);
            sw += w;
            uint32_t q = *(const uint32_t*)(d_h1 + ((size_t)(2 * f + b)) * 128 + 2 * p);
            float2 o1 = h2f(q);
            p1.x = fmaf(w, o1.x, p1.x);
            p1.y = fmaf(w, o1.y, p1.y);
        }
        xps[sub][p] = a;
    }
    __syncthreads();
    if (ok) {
        float2 br = *(const float2*)(bres + 2 * p);
        float accx = p1.x + sw * br.x;
        float accy = p1.y + sw * br.y;
#pragma unroll 8
        for (int k = 0; k < 64; k++) {
            float xk = xps[sub][k];
            float2 w2 = *(const float2*)(Wres + k * 128 + 2 * p);
            accx = fmaf(xk, w2.x, accx);
            accy = fmaf(xk, w2.y, accy);
        }
        *(float2*)(out + ((size_t)b * CN + c) * 128 + 2 * p) = make_float2(accx, accy);
    }
}

// ---------------- launch ----------------
extern "C" void kernel_launch(void* const* d_in, const int* in_sizes, int n_in,
                              void* d_out, int out_size) {
    const float* x       = (const float*)d_in[0];
    const float* adjVal  = (const float*)d_in[1];
    const int*   E_start = (const int*)d_in[3];
    const int*   E_end   = (const int*)d_in[4];
    const int*   asgnIdx = (const int*)d_in[5];
    const float* asgnVal = (const float*)d_in[6];
    const float* W_res   = (const float*)d_in[7];
    const float* b_res   = (const float*)d_in[8];
    const float* W0s     = (const float*)d_in[9];
    const float* W0n     = (const float*)d_in[10];
    const float* b0      = (const float*)d_in[11];
    const float* W1s     = (const float*)d_in[12];
    const float* W1n     = (const float*)d_in[13];
    const float* b1      = (const float*)d_in[14];
    float* out = (float*)d_out;

    const int smG0 = 1024 + 3 * 16384 + 2 * 16384;   // 82944
    const int smG1 = 1024 + 3 * 16384 + 4 * 16384;   // 115712 (2 CTAs/SM)
    cudaFuncSetAttribute(k_gemm<2, true>,  cudaFuncAttributeMaxDynamicSharedMemorySize, smG0);
    cudaFuncSetAttribute(k_gemm<4, false>, cudaFuncAttributeMaxDynamicSharedMemorySize, smG1);

    k_pre<<<PREB, 512>>>(W0s, W0n, W1s, W1n, x, E_start, E_end, adjVal);  // 0
    k_gather64<<<NV / 8, 256>>>();                                        // 1 (resets d_barA)
    k_gemm<2, true><<<GGRID, 256, smG0>>>(b0);                            // 2
    k_gather128<<<NV / 8, 256>>>();                                       // 3 <- ncu capture slot
    k_gemm<4, false><<<GGRID, 256, smG1>>>(b1);                           // 4
    k_final<<<(2 * CN + 3) / 4, 256>>>(x, asgnIdx, asgnVal, W_res, b_res, out); // 5 (zeros counters)
}